// round 2
// baseline (speedup 1.0000x reference)
#include <cuda_runtime.h>
#include <math.h>

// Shapes: [B=4, C=1, D=128, H=192, W=192]; dsc: [4,1,8,12,12] = 4608
#define BB 4
#define DD 128
#define HH 192
#define WW 192
#define SD (HH*WW)          // 36864  (D stride)
#define SH (WW)             // 192    (H stride)
#define NTOT (BB*DD*HH*WW)  // 18,874,368
#define NDSC 4608
#define W4 (WW/4)           // 48 float4 groups per line

// Global accumulators: [0] = sum |y - p|, [1] = sum over 3 axes of (|gy|-|gp|)^2
__device__ double g_acc[2];

__global__ void zero_acc_kernel() {
    g_acc[0] = 0.0;
    g_acc[1] = 0.0;
}

__device__ __forceinline__ float4 ld4(const float* __restrict__ p) {
    return *reinterpret_cast<const float4*>(p);
}

// |grad| difference contribution helper ops on float4 lanes
__device__ __forceinline__ float4 axgrad(float4 plus, float4 minus, float scale) {
    return make_float4(scale * (plus.x - minus.x),
                       scale * (plus.y - minus.y),
                       scale * (plus.z - minus.z),
                       scale * (plus.w - minus.w));
}

// Compute self vec + the three axis gradients for array x at (b,d,h,w0..w0+3)
__device__ __forceinline__ void load_grads(
    const float* __restrict__ x, int base, int d, int h, int w0,
    float4& s, float4& gd, float4& gh, float4& gw)
{
    s = ld4(x + base);

    // D axis
    float4 dp = (d < DD - 1) ? ld4(x + base + SD) : s;
    float4 dm = (d > 0)      ? ld4(x + base - SD) : s;
    float dscale = (d == 0 || d == DD - 1) ? 1.0f : 0.5f;
    gd = axgrad(dp, dm, dscale);

    // H axis
    float4 hp = (h < HH - 1) ? ld4(x + base + SH) : s;
    float4 hm = (h > 0)      ? ld4(x + base - SH) : s;
    float hscale = (h == 0 || h == HH - 1) ? 1.0f : 0.5f;
    gh = axgrad(hp, hm, hscale);

    // W axis: neighbors from registers + 2 scalar edge loads
    float l = (w0 > 0)       ? x[base - 1] : s.x;
    float r = (w0 + 4 < WW)  ? x[base + 4] : s.w;
    gw.x = ((w0 == 0)        ? 1.0f : 0.5f) * (s.y - l);
    gw.y = 0.5f * (s.z - s.x);
    gw.z = 0.5f * (s.w - s.y);
    gw.w = ((w0 + 4 == WW)   ? 1.0f : 0.5f) * (r - s.z);
}

__device__ __forceinline__ float gd_term(float4 gy, float4 gp) {
    float tx = fabsf(gy.x) - fabsf(gp.x);
    float ty = fabsf(gy.y) - fabsf(gp.y);
    float tz = fabsf(gy.z) - fabsf(gp.z);
    float tw = fabsf(gy.w) - fabsf(gp.w);
    return tx * tx + ty * ty + tz * tz + tw * tw;
}

__global__ void __launch_bounds__(256)
vol_kernel(const float* __restrict__ predicts,
           const float* __restrict__ y_data)
{
    int v = blockIdx.x * blockDim.x + threadIdx.x;   // float4 group index
    float l1 = 0.0f;
    float gd = 0.0f;

    if (v < NTOT / 4) {
        int w4 = v % W4;
        int t  = v / W4;
        int h  = t % HH;
        int t2 = t / HH;
        int d  = t2 % DD;
        int b  = t2 / DD;
        int w0 = w4 * 4;
        int base = ((b * DD + d) * HH + h) * WW + w0;

        float4 ys, ygd, ygh, ygw;
        float4 ps, pgd, pgh, pgw;
        load_grads(y_data,   base, d, h, w0, ys, ygd, ygh, ygw);
        load_grads(predicts, base, d, h, w0, ps, pgd, pgh, pgw);

        l1 = fabsf(ys.x - ps.x) + fabsf(ys.y - ps.y)
           + fabsf(ys.z - ps.z) + fabsf(ys.w - ps.w);

        gd = gd_term(ygd, pgd) + gd_term(ygh, pgh) + gd_term(ygw, pgw);
    }

    // warp reduce
    #pragma unroll
    for (int off = 16; off > 0; off >>= 1) {
        l1 += __shfl_down_sync(0xFFFFFFFFu, l1, off);
        gd += __shfl_down_sync(0xFFFFFFFFu, gd, off);
    }

    __shared__ float s_l1[8];
    __shared__ float s_gd[8];
    int lane = threadIdx.x & 31;
    int wid  = threadIdx.x >> 5;
    if (lane == 0) { s_l1[wid] = l1; s_gd[wid] = gd; }
    __syncthreads();

    if (wid == 0) {
        l1 = (lane < 8) ? s_l1[lane] : 0.0f;
        gd = (lane < 8) ? s_gd[lane] : 0.0f;
        #pragma unroll
        for (int off = 4; off > 0; off >>= 1) {
            l1 += __shfl_down_sync(0xFFFFFFFFu, l1, off);
            gd += __shfl_down_sync(0xFFFFFFFFu, gd, off);
        }
        if (lane == 0) {
            atomicAdd(&g_acc[0], (double)l1);
            atomicAdd(&g_acc[1], (double)gd);
        }
    }
}

__global__ void __launch_bounds__(256)
finalize_kernel(const float* __restrict__ dsc_fake,
                const float* __restrict__ zeros,
                float* __restrict__ out)
{
    float s = 0.0f;
    for (int i = threadIdx.x; i < NDSC; i += 256) {
        float x = dsc_fake[i];
        float z = zeros[i];
        s += fmaxf(x, 0.0f) - x * z + log1pf(expf(-fabsf(x)));
    }
    #pragma unroll
    for (int off = 16; off > 0; off >>= 1)
        s += __shfl_down_sync(0xFFFFFFFFu, s, off);

    __shared__ float sh[8];
    int lane = threadIdx.x & 31;
    int wid  = threadIdx.x >> 5;
    if (lane == 0) sh[wid] = s;
    __syncthreads();
    if (wid == 0) {
        s = (lane < 8) ? sh[lane] : 0.0f;
        #pragma unroll
        for (int off = 4; off > 0; off >>= 1)
            s += __shfl_down_sync(0xFFFFFFFFu, s, off);
        if (lane == 0) {
            double bce = (double)s / (double)NDSC;
            double l1m = g_acc[0] / (double)NTOT;
            double gdm = g_acc[1] / (double)NTOT;
            out[0] = (float)(bce + 100.0 * l1m + 100.0 * gdm);
        }
    }
}

extern "C" void kernel_launch(void* const* d_in, const int* in_sizes, int n_in,
                              void* d_out, int out_size)
{
    const float* dsc_fake = (const float*)d_in[0];
    const float* predicts = (const float*)d_in[1];
    const float* y_data   = (const float*)d_in[2];
    const float* zeros    = (const float*)d_in[3];
    float* out = (float*)d_out;

    zero_acc_kernel<<<1, 1>>>();

    const int nvec = NTOT / 4;                 // 4,718,592
    const int threads = 256;
    const int blocks = (nvec + threads - 1) / threads;  // 18,432
    vol_kernel<<<blocks, threads>>>(predicts, y_data);

    finalize_kernel<<<1, 256>>>(dsc_fake, zeros, out);
}

// round 3
// speedup vs baseline: 2.0339x; 2.0339x over previous
#include <cuda_runtime.h>
#include <math.h>

// Shapes: [B=4, C=1, D=128, H=192, W=192]; dsc: [4,1,8,12,12] = 4608
#define BB 4
#define DD 128
#define HH 192
#define WW 192
#define SD (HH*WW)          // 36864  (D stride, elements)
#define SH (WW)             // 192    (H stride, elements)
#define NTOT (BB*DD*HH*WW)  // 18,874,368
#define NDSC 4608
#define W4 (WW/4)           // 48 float4 groups per W line

#define DCH 32              // d-planes per thread (rolling window)
#define NCHUNK (DD/DCH)     // 4
#define NCOL (BB*HH*W4)     // 36,864 columns
#define NTHREADS (NCOL*NCHUNK)   // 147,456
#define TPB 256
#define NBLK (NTHREADS/TPB)      // 576 (exact)

// Per-block partial sums: [,0]=sum|y-p|, [,1]=sum gd terms
__device__ double g_part[NBLK][2];

__device__ __forceinline__ float4 ld4(const float* __restrict__ p) {
    return *reinterpret_cast<const float4*>(p);
}

__device__ __forceinline__ float4 axgrad(float4 plus, float4 minus, float scale) {
    return make_float4(scale * (plus.x - minus.x),
                       scale * (plus.y - minus.y),
                       scale * (plus.z - minus.z),
                       scale * (plus.w - minus.w));
}

__device__ __forceinline__ float gd_term(float4 gy, float4 gp) {
    float tx = fabsf(gy.x) - fabsf(gp.x);
    float ty = fabsf(gy.y) - fabsf(gp.y);
    float tz = fabsf(gy.z) - fabsf(gp.z);
    float tw = fabsf(gy.w) - fabsf(gp.w);
    return tx * tx + ty * ty + tz * tz + tw * tw;
}

__global__ void __launch_bounds__(TPB)
vol_kernel(const float* __restrict__ predicts,
           const float* __restrict__ y_data)
{
    const int tid = blockIdx.x * TPB + threadIdx.x;   // exact fit, no bounds check
    const int w4 = tid % W4;
    int t  = tid / W4;
    const int h  = t % HH;
    t /= HH;
    const int dc = t % NCHUNK;
    const int b  = t / NCHUNK;

    const int w0 = w4 * 4;
    const int d0 = dc * DCH;
    const long ofs = ((long)(b * DD + d0) * HH + h) * WW + w0;
    const float* __restrict__ yb = y_data   + ofs;
    const float* __restrict__ pb = predicts + ofs;

    // H-edge clamp trick: offset 0 => neighbor := self, scale 1.0 => one-sided diff
    const float hscale = (h == 0 || h == HH - 1) ? 1.0f : 0.5f;
    const int hp_off = (h < HH - 1) ?  SH : 0;
    const int hm_off = (h > 0)      ? -SH : 0;

    const bool wl_ok = (w0 > 0);
    const bool wr_ok = (w0 + 4 < WW);
    const float wl_scale = wl_ok ? 0.5f : 1.0f;
    const float wr_scale = wr_ok ? 0.5f : 1.0f;

    // Rolling D window
    float4 ycur  = ld4(yb);
    float4 yprev = (d0 > 0) ? ld4(yb - SD) : ycur;
    float4 pcur  = ld4(pb);
    float4 pprev = (d0 > 0) ? ld4(pb - SD) : pcur;

    float l1_acc = 0.0f;
    float gd_acc = 0.0f;

    for (int i = 0; i < DCH; i++) {
        const int d = d0 + i;
        const int next_off = (d < DD - 1) ? SD : 0;   // clamp at d-edge
        const float dscale  = (d == 0 || d == DD - 1) ? 1.0f : 0.5f;
        const float* __restrict__ yp_ = yb + i * SD;
        const float* __restrict__ pp_ = pb + i * SD;

        // Issue all loads up front (10 independent requests)
        float4 ynext = ld4(yp_ + next_off);
        float4 pnext = ld4(pp_ + next_off);
        float4 yhp = ld4(yp_ + hp_off);
        float4 yhm = ld4(yp_ + hm_off);
        float4 php = ld4(pp_ + hp_off);
        float4 phm = ld4(pp_ + hm_off);
        float  yl = wl_ok ? yp_[-1] : ycur.x;
        float  yr = wr_ok ? yp_[4]  : ycur.w;
        float  pl = wl_ok ? pp_[-1] : pcur.x;
        float  pr = wr_ok ? pp_[4]  : pcur.w;

        // D gradients (registers for prev, just-loaded next)
        float4 ygd = axgrad(ynext, yprev, dscale);
        float4 pgd = axgrad(pnext, pprev, dscale);

        // H gradients
        float4 ygh = axgrad(yhp, yhm, hscale);
        float4 pgh = axgrad(php, phm, hscale);

        // W gradients (all from registers)
        float4 ygw, pgw;
        ygw.x = wl_scale * (ycur.y - yl);
        ygw.y = 0.5f * (ycur.z - ycur.x);
        ygw.z = 0.5f * (ycur.w - ycur.y);
        ygw.w = wr_scale * (yr - ycur.z);
        pgw.x = wl_scale * (pcur.y - pl);
        pgw.y = 0.5f * (pcur.z - pcur.x);
        pgw.z = 0.5f * (pcur.w - pcur.y);
        pgw.w = wr_scale * (pr - pcur.z);

        l1_acc += fabsf(ycur.x - pcur.x) + fabsf(ycur.y - pcur.y)
                + fabsf(ycur.z - pcur.z) + fabsf(ycur.w - pcur.w);

        gd_acc += gd_term(ygd, pgd) + gd_term(ygh, pgh) + gd_term(ygw, pgw);

        yprev = ycur; ycur = ynext;
        pprev = pcur; pcur = pnext;
    }

    // Block reduction
    #pragma unroll
    for (int off = 16; off > 0; off >>= 1) {
        l1_acc += __shfl_down_sync(0xFFFFFFFFu, l1_acc, off);
        gd_acc += __shfl_down_sync(0xFFFFFFFFu, gd_acc, off);
    }

    __shared__ float s_l1[8];
    __shared__ float s_gd[8];
    const int lane = threadIdx.x & 31;
    const int wid  = threadIdx.x >> 5;
    if (lane == 0) { s_l1[wid] = l1_acc; s_gd[wid] = gd_acc; }
    __syncthreads();

    if (wid == 0) {
        l1_acc = (lane < 8) ? s_l1[lane] : 0.0f;
        gd_acc = (lane < 8) ? s_gd[lane] : 0.0f;
        #pragma unroll
        for (int off = 4; off > 0; off >>= 1) {
            l1_acc += __shfl_down_sync(0xFFFFFFFFu, l1_acc, off);
            gd_acc += __shfl_down_sync(0xFFFFFFFFu, gd_acc, off);
        }
        if (lane == 0) {
            g_part[blockIdx.x][0] = (double)l1_acc;
            g_part[blockIdx.x][1] = (double)gd_acc;
        }
    }
}

__global__ void __launch_bounds__(256)
finalize_kernel(const float* __restrict__ dsc_fake,
                const float* __restrict__ zeros,
                float* __restrict__ out)
{
    // BCE over 4608 logits
    float s = 0.0f;
    for (int i = threadIdx.x; i < NDSC; i += 256) {
        float x = dsc_fake[i];
        float z = zeros[i];
        s += fmaxf(x, 0.0f) - x * z + log1pf(expf(-fabsf(x)));
    }

    // Partial sums from vol_kernel (double precision)
    double l1d = 0.0, gdd = 0.0;
    for (int i = threadIdx.x; i < NBLK; i += 256) {
        l1d += g_part[i][0];
        gdd += g_part[i][1];
    }

    #pragma unroll
    for (int off = 16; off > 0; off >>= 1) {
        s   += __shfl_down_sync(0xFFFFFFFFu, s, off);
        l1d += __shfl_down_sync(0xFFFFFFFFu, l1d, off);
        gdd += __shfl_down_sync(0xFFFFFFFFu, gdd, off);
    }

    __shared__ float  sh_s[8];
    __shared__ double sh_l1[8];
    __shared__ double sh_gd[8];
    const int lane = threadIdx.x & 31;
    const int wid  = threadIdx.x >> 5;
    if (lane == 0) { sh_s[wid] = s; sh_l1[wid] = l1d; sh_gd[wid] = gdd; }
    __syncthreads();

    if (wid == 0) {
        s   = (lane < 8) ? sh_s[lane]  : 0.0f;
        l1d = (lane < 8) ? sh_l1[lane] : 0.0;
        gdd = (lane < 8) ? sh_gd[lane] : 0.0;
        #pragma unroll
        for (int off = 4; off > 0; off >>= 1) {
            s   += __shfl_down_sync(0xFFFFFFFFu, s, off);
            l1d += __shfl_down_sync(0xFFFFFFFFu, l1d, off);
            gdd += __shfl_down_sync(0xFFFFFFFFu, gdd, off);
        }
        if (lane == 0) {
            double bce = (double)s / (double)NDSC;
            double l1m = l1d / (double)NTOT;
            double gdm = gdd / (double)NTOT;
            out[0] = (float)(bce + 100.0 * l1m + 100.0 * gdm);
        }
    }
}

extern "C" void kernel_launch(void* const* d_in, const int* in_sizes, int n_in,
                              void* d_out, int out_size)
{
    const float* dsc_fake = (const float*)d_in[0];
    const float* predicts = (const float*)d_in[1];
    const float* y_data   = (const float*)d_in[2];
    const float* zeros    = (const float*)d_in[3];
    float* out = (float*)d_out;

    vol_kernel<<<NBLK, TPB>>>(predicts, y_data);
    finalize_kernel<<<1, 256>>>(dsc_fake, zeros, out);
}

// round 4
// speedup vs baseline: 2.1146x; 1.0396x over previous
#include <cuda_runtime.h>
#include <math.h>

// Shapes: [B=4, C=1, D=128, H=192, W=192]; dsc: [4,1,8,12,12] = 4608
#define BB 4
#define DD 128
#define HH 192
#define WW 192
#define SD (HH*WW)          // 36864  (D stride, elements)
#define SH (WW)             // 192    (H stride, elements)
#define NTOT (BB*DD*HH*WW)  // 18,874,368
#define NDSC 4608
#define W4 (WW/4)           // 48 float4 groups per W line

#define DCH 16              // d-planes per thread (rolling window)
#define NCHUNK (DD/DCH)     // 8
#define NCOL (BB*HH*W4)     // 36,864 columns
#define NTHREADS (NCOL*NCHUNK)   // 294,912
#define TPB 256
#define NBLK (NTHREADS/TPB)      // 1152 (exact)

// Per-block partial sums: [,0]=sum|y-p|, [,1]=sum gd terms
__device__ double g_part[NBLK][2];
__device__ float  g_bce;        // BCE partial (written by block 0)
__device__ int    g_count;      // zero-init; last block restores to 0

__device__ __forceinline__ float4 ld4(const float* __restrict__ p) {
    return *reinterpret_cast<const float4*>(p);
}

__device__ __forceinline__ float4 axgrad(float4 plus, float4 minus, float scale) {
    return make_float4(scale * (plus.x - minus.x),
                       scale * (plus.y - minus.y),
                       scale * (plus.z - minus.z),
                       scale * (plus.w - minus.w));
}

__device__ __forceinline__ float gd_term(float4 gy, float4 gp) {
    float tx = fabsf(gy.x) - fabsf(gp.x);
    float ty = fabsf(gy.y) - fabsf(gp.y);
    float tz = fabsf(gy.z) - fabsf(gp.z);
    float tw = fabsf(gy.w) - fabsf(gp.w);
    return tx * tx + ty * ty + tz * tz + tw * tw;
}

__global__ void __launch_bounds__(TPB)
vol_kernel(const float* __restrict__ predicts,
           const float* __restrict__ y_data,
           const float* __restrict__ dsc_fake,
           const float* __restrict__ zeros,
           float* __restrict__ out)
{
    __shared__ float  s_a[8];
    __shared__ float  s_b[8];
    __shared__ bool   s_last;
    const int lane = threadIdx.x & 31;
    const int wid  = threadIdx.x >> 5;

    // ---- Block 0: compute BCE in parallel with everyone's main work ----
    if (blockIdx.x == 0) {
        float s = 0.0f;
        for (int i = threadIdx.x; i < NDSC; i += TPB) {
            float x = dsc_fake[i];
            float z = zeros[i];
            s += fmaxf(x, 0.0f) - x * z + log1pf(expf(-fabsf(x)));
        }
        #pragma unroll
        for (int off = 16; off > 0; off >>= 1)
            s += __shfl_down_sync(0xFFFFFFFFu, s, off);
        if (lane == 0) s_a[wid] = s;
        __syncthreads();
        if (wid == 0) {
            s = (lane < 8) ? s_a[lane] : 0.0f;
            #pragma unroll
            for (int off = 4; off > 0; off >>= 1)
                s += __shfl_down_sync(0xFFFFFFFFu, s, off);
            if (lane == 0) g_bce = s;
        }
        __syncthreads();
    }

    // ---- Main fused stencil + reduction ----
    const int tid = blockIdx.x * TPB + threadIdx.x;   // exact fit
    const int w4 = tid % W4;
    int t  = tid / W4;
    const int h  = t % HH;
    t /= HH;
    const int dc = t % NCHUNK;
    const int b  = t / NCHUNK;

    const int w0 = w4 * 4;
    const int d0 = dc * DCH;
    const long ofs = ((long)(b * DD + d0) * HH + h) * WW + w0;
    const float* __restrict__ yb = y_data   + ofs;
    const float* __restrict__ pb = predicts + ofs;

    const float hscale = (h == 0 || h == HH - 1) ? 1.0f : 0.5f;
    const int hp_off = (h < HH - 1) ?  SH : 0;
    const int hm_off = (h > 0)      ? -SH : 0;

    const bool wl_ok = (w0 > 0);
    const bool wr_ok = (w0 + 4 < WW);
    const float wl_scale = wl_ok ? 0.5f : 1.0f;
    const float wr_scale = wr_ok ? 0.5f : 1.0f;

    float4 ycur  = ld4(yb);
    float4 yprev = (d0 > 0) ? ld4(yb - SD) : ycur;
    float4 pcur  = ld4(pb);
    float4 pprev = (d0 > 0) ? ld4(pb - SD) : pcur;

    float l1_acc = 0.0f;
    float gd_acc = 0.0f;

    #pragma unroll 4
    for (int i = 0; i < DCH; i++) {
        const int d = d0 + i;
        const int next_off = (d < DD - 1) ? SD : 0;
        const float dscale  = (d == 0 || d == DD - 1) ? 1.0f : 0.5f;
        const float* __restrict__ yp_ = yb + i * SD;
        const float* __restrict__ pp_ = pb + i * SD;

        float4 ynext = ld4(yp_ + next_off);
        float4 pnext = ld4(pp_ + next_off);
        float4 yhp = ld4(yp_ + hp_off);
        float4 yhm = ld4(yp_ + hm_off);
        float4 php = ld4(pp_ + hp_off);
        float4 phm = ld4(pp_ + hm_off);
        float  yl = wl_ok ? yp_[-1] : ycur.x;
        float  yr = wr_ok ? yp_[4]  : ycur.w;
        float  pl = wl_ok ? pp_[-1] : pcur.x;
        float  pr = wr_ok ? pp_[4]  : pcur.w;

        float4 ygd = axgrad(ynext, yprev, dscale);
        float4 pgd = axgrad(pnext, pprev, dscale);
        float4 ygh = axgrad(yhp, yhm, hscale);
        float4 pgh = axgrad(php, phm, hscale);

        float4 ygw, pgw;
        ygw.x = wl_scale * (ycur.y - yl);
        ygw.y = 0.5f * (ycur.z - ycur.x);
        ygw.z = 0.5f * (ycur.w - ycur.y);
        ygw.w = wr_scale * (yr - ycur.z);
        pgw.x = wl_scale * (pcur.y - pl);
        pgw.y = 0.5f * (pcur.z - pcur.x);
        pgw.z = 0.5f * (pcur.w - pcur.y);
        pgw.w = wr_scale * (pr - pcur.z);

        l1_acc += fabsf(ycur.x - pcur.x) + fabsf(ycur.y - pcur.y)
                + fabsf(ycur.z - pcur.z) + fabsf(ycur.w - pcur.w);

        gd_acc += gd_term(ygd, pgd) + gd_term(ygh, pgh) + gd_term(ygw, pgw);

        yprev = ycur; ycur = ynext;
        pprev = pcur; pcur = pnext;
    }

    // ---- Block reduction ----
    #pragma unroll
    for (int off = 16; off > 0; off >>= 1) {
        l1_acc += __shfl_down_sync(0xFFFFFFFFu, l1_acc, off);
        gd_acc += __shfl_down_sync(0xFFFFFFFFu, gd_acc, off);
    }
    if (lane == 0) { s_a[wid] = l1_acc; s_b[wid] = gd_acc; }
    __syncthreads();

    if (wid == 0) {
        l1_acc = (lane < 8) ? s_a[lane] : 0.0f;
        gd_acc = (lane < 8) ? s_b[lane] : 0.0f;
        #pragma unroll
        for (int off = 4; off > 0; off >>= 1) {
            l1_acc += __shfl_down_sync(0xFFFFFFFFu, l1_acc, off);
            gd_acc += __shfl_down_sync(0xFFFFFFFFu, gd_acc, off);
        }
        if (lane == 0) {
            g_part[blockIdx.x][0] = (double)l1_acc;
            g_part[blockIdx.x][1] = (double)gd_acc;
        }
    }

    // ---- Last-block-done final reduction ----
    if (threadIdx.x == 0) {
        __threadfence();                         // g_part / g_bce visible
        int prev = atomicAdd(&g_count, 1);
        s_last = (prev == NBLK - 1);
    }
    __syncthreads();

    if (s_last) {
        double l1d = 0.0, gdd = 0.0;
        for (int i = threadIdx.x; i < NBLK; i += TPB) {
            l1d += g_part[i][0];
            gdd += g_part[i][1];
        }
        #pragma unroll
        for (int off = 16; off > 0; off >>= 1) {
            l1d += __shfl_down_sync(0xFFFFFFFFu, l1d, off);
            gdd += __shfl_down_sync(0xFFFFFFFFu, gdd, off);
        }
        __shared__ double sh_l1[8];
        __shared__ double sh_gd[8];
        if (lane == 0) { sh_l1[wid] = l1d; sh_gd[wid] = gdd; }
        __syncthreads();
        if (wid == 0) {
            l1d = (lane < 8) ? sh_l1[lane] : 0.0;
            gdd = (lane < 8) ? sh_gd[lane] : 0.0;
            #pragma unroll
            for (int off = 4; off > 0; off >>= 1) {
                l1d += __shfl_down_sync(0xFFFFFFFFu, l1d, off);
                gdd += __shfl_down_sync(0xFFFFFFFFu, gdd, off);
            }
            if (lane == 0) {
                double bce = (double)g_bce / (double)NDSC;
                double l1m = l1d / (double)NTOT;
                double gdm = gdd / (double)NTOT;
                out[0] = (float)(bce + 100.0 * l1m + 100.0 * gdm);
                g_count = 0;   // restore for deterministic graph replay
            }
        }
    }
}

extern "C" void kernel_launch(void* const* d_in, const int* in_sizes, int n_in,
                              void* d_out, int out_size)
{
    const float* dsc_fake = (const float*)d_in[0];
    const float* predicts = (const float*)d_in[1];
    const float* y_data   = (const float*)d_in[2];
    const float* zeros    = (const float*)d_in[3];
    float* out = (float*)d_out;

    vol_kernel<<<NBLK, TPB>>>(predicts, y_data, dsc_fake, zeros, out);
}

// round 6
// speedup vs baseline: 2.3390x; 1.1062x over previous
#include <cuda_runtime.h>
#include <math.h>

// Shapes: [B=4, C=1, D=128, H=192, W=192]; dsc: [4,1,8,12,12] = 4608
#define BB 4
#define DD 128
#define HH 192
#define WW 192
#define SD (HH*WW)          // 36864  (D stride, elements)
#define SH (WW)             // 192    (H stride, elements)
#define NTOT (BB*DD*HH*WW)  // 18,874,368
#define NDSC 4608
#define W4 (WW/4)           // 48 float4 groups per W line

#define DCH 16              // d-planes per thread (rolling window)
#define NCHUNK (DD/DCH)     // 8
#define NCOL (BB*HH*W4)     // 36,864 columns
#define NTHREADS (NCOL*NCHUNK)   // 294,912
#define TPB 256
#define NBLK (NTHREADS/TPB)      // 1152 (exact)

// Per-block partial sums: [,0]=sum|y-p|, [,1]=sum gd terms
__device__ double g_part[NBLK][2];
__device__ float  g_bce;        // BCE partial (written by block 0)
__device__ int    g_count;      // zero-init; last block restores to 0

__device__ __forceinline__ float4 ld4(const float* __restrict__ p) {
    return *reinterpret_cast<const float4*>(p);
}

__device__ __forceinline__ float4 axgrad(float4 plus, float4 minus, float scale) {
    return make_float4(scale * (plus.x - minus.x),
                       scale * (plus.y - minus.y),
                       scale * (plus.z - minus.z),
                       scale * (plus.w - minus.w));
}

__device__ __forceinline__ float gd_term(float4 gy, float4 gp) {
    float tx = fabsf(gy.x) - fabsf(gp.x);
    float ty = fabsf(gy.y) - fabsf(gp.y);
    float tz = fabsf(gy.z) - fabsf(gp.z);
    float tw = fabsf(gy.w) - fabsf(gp.w);
    return tx * tx + ty * ty + tz * tz + tw * tw;
}

__global__ void __launch_bounds__(TPB, 4)   // force <=64 regs -> 4 blocks/SM
vol_kernel(const float* __restrict__ predicts,
           const float* __restrict__ y_data,
           const float* __restrict__ dsc_fake,
           const float* __restrict__ zeros,
           float* __restrict__ out)
{
    __shared__ float  s_a[8];
    __shared__ float  s_b[8];
    __shared__ bool   s_last;
    const int lane = threadIdx.x & 31;
    const int wid  = threadIdx.x >> 5;

    // ---- Block 0: compute BCE in parallel with everyone's main work ----
    if (blockIdx.x == 0) {
        float s = 0.0f;
        for (int i = threadIdx.x; i < NDSC; i += TPB) {
            float x = dsc_fake[i];
            float z = zeros[i];
            s += fmaxf(x, 0.0f) - x * z + log1pf(expf(-fabsf(x)));
        }
        #pragma unroll
        for (int off = 16; off > 0; off >>= 1)
            s += __shfl_down_sync(0xFFFFFFFFu, s, off);
        if (lane == 0) s_a[wid] = s;
        __syncthreads();
        if (wid == 0) {
            s = (lane < 8) ? s_a[lane] : 0.0f;
            #pragma unroll
            for (int off = 4; off > 0; off >>= 1)
                s += __shfl_down_sync(0xFFFFFFFFu, s, off);
            if (lane == 0) g_bce = s;
        }
        __syncthreads();
    }

    // ---- Main fused stencil + reduction ----
    const int tid = blockIdx.x * TPB + threadIdx.x;   // exact fit
    const int w4 = tid % W4;
    int t  = tid / W4;
    const int h  = t % HH;
    t /= HH;
    const int dc = t % NCHUNK;
    const int b  = t / NCHUNK;

    const int w0 = w4 * 4;
    const int d0 = dc * DCH;
    const long ofs = ((long)(b * DD + d0) * HH + h) * WW + w0;
    const float* __restrict__ yp_ = y_data   + ofs;
    const float* __restrict__ pp_ = predicts + ofs;

    const float hscale = (h == 0 || h == HH - 1) ? 1.0f : 0.5f;
    const int hp_off = (h < HH - 1) ?  SH : 0;
    const int hm_off = (h > 0)      ? -SH : 0;

    const bool wl_ok = (w0 > 0);
    const bool wr_ok = (w0 + 4 < WW);
    const float wl_scale = wl_ok ? 0.5f : 1.0f;
    const float wr_scale = wr_ok ? 0.5f : 1.0f;

    float4 ycur  = ld4(yp_);
    float4 yprev = (d0 > 0) ? ld4(yp_ - SD) : ycur;
    float4 pcur  = ld4(pp_);
    float4 pprev = (d0 > 0) ? ld4(pp_ - SD) : pcur;

    float l1_acc = 0.0f;
    float gd_acc = 0.0f;

    #pragma unroll 2
    for (int i = 0; i < DCH; i++) {
        const int d = d0 + i;
        const int next_off = (d < DD - 1) ? SD : 0;
        const float dscale  = (d == 0 || d == DD - 1) ? 1.0f : 0.5f;

        float4 ynext = ld4(yp_ + next_off);
        float4 pnext = ld4(pp_ + next_off);
        float4 yhp = ld4(yp_ + hp_off);
        float4 yhm = ld4(yp_ + hm_off);
        float4 php = ld4(pp_ + hp_off);
        float4 phm = ld4(pp_ + hm_off);
        float  yl = wl_ok ? yp_[-1] : ycur.x;
        float  yr = wr_ok ? yp_[4]  : ycur.w;
        float  pl = wl_ok ? pp_[-1] : pcur.x;
        float  pr = wr_ok ? pp_[4]  : pcur.w;

        float4 ygd = axgrad(ynext, yprev, dscale);
        float4 pgd = axgrad(pnext, pprev, dscale);
        float4 ygh = axgrad(yhp, yhm, hscale);
        float4 pgh = axgrad(php, phm, hscale);

        float4 ygw, pgw;
        ygw.x = wl_scale * (ycur.y - yl);
        ygw.y = 0.5f * (ycur.z - ycur.x);
        ygw.z = 0.5f * (ycur.w - ycur.y);
        ygw.w = wr_scale * (yr - ycur.z);
        pgw.x = wl_scale * (pcur.y - pl);
        pgw.y = 0.5f * (pcur.z - pcur.x);
        pgw.z = 0.5f * (pcur.w - pcur.y);
        pgw.w = wr_scale * (pr - pcur.z);

        l1_acc += fabsf(ycur.x - pcur.x) + fabsf(ycur.y - pcur.y)
                + fabsf(ycur.z - pcur.z) + fabsf(ycur.w - pcur.w);

        gd_acc += gd_term(ygd, pgd) + gd_term(ygh, pgh) + gd_term(ygw, pgw);

        yprev = ycur; ycur = ynext;
        pprev = pcur; pcur = pnext;
        yp_ += SD; pp_ += SD;
    }

    // ---- Block reduction ----
    #pragma unroll
    for (int off = 16; off > 0; off >>= 1) {
        l1_acc += __shfl_down_sync(0xFFFFFFFFu, l1_acc, off);
        gd_acc += __shfl_down_sync(0xFFFFFFFFu, gd_acc, off);
    }
    if (lane == 0) { s_a[wid] = l1_acc; s_b[wid] = gd_acc; }
    __syncthreads();

    if (wid == 0) {
        l1_acc = (lane < 8) ? s_a[lane] : 0.0f;
        gd_acc = (lane < 8) ? s_b[lane] : 0.0f;
        #pragma unroll
        for (int off = 4; off > 0; off >>= 1) {
            l1_acc += __shfl_down_sync(0xFFFFFFFFu, l1_acc, off);
            gd_acc += __shfl_down_sync(0xFFFFFFFFu, gd_acc, off);
        }
        if (lane == 0) {
            g_part[blockIdx.x][0] = (double)l1_acc;
            g_part[blockIdx.x][1] = (double)gd_acc;
        }
    }

    // ---- Last-block-done final reduction ----
    if (threadIdx.x == 0) {
        __threadfence();                         // g_part / g_bce visible
        int prev = atomicAdd(&g_count, 1);
        s_last = (prev == NBLK - 1);
    }
    __syncthreads();

    if (s_last) {
        double l1d = 0.0, gdd = 0.0;
        for (int i = threadIdx.x; i < NBLK; i += TPB) {
            l1d += g_part[i][0];
            gdd += g_part[i][1];
        }
        #pragma unroll
        for (int off = 16; off > 0; off >>= 1) {
            l1d += __shfl_down_sync(0xFFFFFFFFu, l1d, off);
            gdd += __shfl_down_sync(0xFFFFFFFFu, gdd, off);
        }
        __shared__ double sh_l1[8];
        __shared__ double sh_gd[8];
        if (lane == 0) { sh_l1[wid] = l1d; sh_gd[wid] = gdd; }
        __syncthreads();
        if (wid == 0) {
            l1d = (lane < 8) ? sh_l1[lane] : 0.0;
            gdd = (lane < 8) ? sh_gd[lane] : 0.0;
            #pragma unroll
            for (int off = 4; off > 0; off >>= 1) {
                l1d += __shfl_down_sync(0xFFFFFFFFu, l1d, off);
                gdd += __shfl_down_sync(0xFFFFFFFFu, gdd, off);
            }
            if (lane == 0) {
                double bce = (double)g_bce / (double)NDSC;
                double l1m = l1d / (double)NTOT;
                double gdm = gdd / (double)NTOT;
                out[0] = (float)(bce + 100.0 * l1m + 100.0 * gdm);
                g_count = 0;   // restore for deterministic graph replay
            }
        }
    }
}

extern "C" void kernel_launch(void* const* d_in, const int* in_sizes, int n_in,
                              void* d_out, int out_size)
{
    const float* dsc_fake = (const float*)d_in[0];
    const float* predicts = (const float*)d_in[1];
    const float* y_data   = (const float*)d_in[2];
    const float* zeros    = (const float*)d_in[3];
    float* out = (float*)d_out;

    vol_kernel<<<NBLK, TPB>>>(predicts, y_data, dsc_fake, zeros, out);
}

// round 9
// speedup vs baseline: 2.6371x; 1.1274x over previous
#include <cuda_runtime.h>
#include <math.h>

// Shapes: [B=4, C=1, D=128, H=192, W=192]; dsc: [4,1,8,12,12] = 4608
#define BB 4
#define DD 128
#define HH 192
#define WW 192
#define SD (HH*WW)          // 36864  (D stride, elements)
#define SH (WW)             // 192    (H stride, elements)
#define NTOT (BB*DD*HH*WW)  // 18,874,368
#define NDSC 4608

#define W2 (WW/2)           // 96 float2 groups per W line
#define H2 (HH/2)           // 96 row pairs
#define DCH 16              // d-planes per thread (rolling window)
#define NCHUNK (DD/DCH)     // 8
#define NTHREADS (BB*H2*W2*NCHUNK)   // 294,912
#define TPB 256
#define NBLK (NTHREADS/TPB)          // 1152 (exact)

__device__ double g_part[NBLK][2];
__device__ float  g_bce;
__device__ int    g_count;   // zero-init; last block restores to 0

__device__ __forceinline__ float2 ld2(const float* __restrict__ p) {
    return *reinterpret_cast<const float2*>(p);
}

__global__ void __launch_bounds__(TPB, 4)
vol_kernel(const float* __restrict__ predicts,
           const float* __restrict__ y_data,
           const float* __restrict__ dsc_fake,
           const float* __restrict__ zeros,
           float* __restrict__ out)
{
    __shared__ float s_a[8];
    __shared__ float s_b[8];
    __shared__ bool  s_last;
    const int lane = threadIdx.x & 31;
    const int wid  = threadIdx.x >> 5;

    // ---- Block 0: BCE in parallel with everyone's main work ----
    if (blockIdx.x == 0) {
        float s = 0.0f;
        for (int i = threadIdx.x; i < NDSC; i += TPB) {
            float x = dsc_fake[i];
            float z = zeros[i];
            s += fmaxf(x, 0.0f) - x * z + log1pf(expf(-fabsf(x)));
        }
        #pragma unroll
        for (int off = 16; off > 0; off >>= 1)
            s += __shfl_down_sync(0xFFFFFFFFu, s, off);
        if (lane == 0) s_a[wid] = s;
        __syncthreads();
        if (wid == 0) {
            s = (lane < 8) ? s_a[lane] : 0.0f;
            #pragma unroll
            for (int off = 4; off > 0; off >>= 1)
                s += __shfl_down_sync(0xFFFFFFFFu, s, off);
            if (lane == 0) g_bce = s;
        }
        __syncthreads();
    }

    // ---- Index decode: thread owns rows (h0, h0+1), cols (w0, w0+1) ----
    const int tid = blockIdx.x * TPB + threadIdx.x;   // exact fit
    const int w2 = tid % W2;
    int t  = tid / W2;
    const int h2 = t % H2;
    t /= H2;
    const int dc = t % NCHUNK;
    const int b  = t / NCHUNK;

    const int h0 = 2 * h2;           // even, <= 190
    const int w0 = 2 * w2;
    const int d0 = dc * DCH;

    const long ofs = ((long)(b * DD + d0) * HH + h0) * WW + w0;
    const float* __restrict__ y0 = y_data   + ofs;   // row h0; row h1 = y0+SH
    const float* __restrict__ p0 = predicts + ofs;

    const bool h0e = (h0 == 0);
    const bool h1e = (h2 == H2 - 1);     // h0+1 == 191
    const bool w0e = (w2 == 0);
    const bool w1e = (w2 == W2 - 1);
    const float hs0 = h0e ? 1.0f : 0.25f;   // scale^2 for row h0 H-grad
    const float hs1 = h1e ? 1.0f : 0.25f;
    const float wl2 = w0e ? 1.0f : 0.25f;
    const float wr2 = w1e ? 1.0f : 0.25f;
    const bool lload = (lane == 0)  && !w0e;   // warp spans one row: 96 = 3*32
    const bool rload = (lane == 31) && !w1e;

    // Rolling D windows (prev, cur) per row per array
    float2 y0c = ld2(y0);
    float2 y1c = ld2(y0 + SH);
    float2 p0c = ld2(p0);
    float2 p1c = ld2(p0 + SH);
    float2 y0p = (d0 > 0) ? ld2(y0 - SD)      : y0c;
    float2 y1p = (d0 > 0) ? ld2(y0 + SH - SD) : y1c;
    float2 p0p = (d0 > 0) ? ld2(p0 - SD)      : p0c;
    float2 p1p = (d0 > 0) ? ld2(p0 + SH - SD) : p1c;

    float l1_acc = 0.0f;
    float gd_acc = 0.0f;

    #pragma unroll 2
    for (int i = 0; i < DCH; i++) {
        const int d = d0 + i;
        const int no  = (d < DD - 1) ? SD : 0;
        const float ds2 = (d == 0 || d == DD - 1) ? 1.0f : 0.25f;

        // D-neighbors (next plane), 4 streams
        float2 y0n = ld2(y0 + no);
        float2 y1n = ld2(y0 + SH + no);
        float2 p0n = ld2(p0 + no);
        float2 p1n = ld2(p0 + SH + no);

        // H-halos: only the outer rows need loads (warp-uniform predicates)
        float2 yhm = h0e ? y0c : ld2(y0 - SH);        // row h0-1
        float2 phm = h0e ? p0c : ld2(p0 - SH);
        float2 yhp = h1e ? y1c : ld2(y0 + 2 * SH);    // row h1+1
        float2 php = h1e ? p1c : ld2(p0 + 2 * SH);

        // W-halos via warp shuffle of neighbor lane's registers
        float y0l = __shfl_up_sync(0xFFFFFFFFu, y0c.y, 1);
        float y1l = __shfl_up_sync(0xFFFFFFFFu, y1c.y, 1);
        float p0l = __shfl_up_sync(0xFFFFFFFFu, p0c.y, 1);
        float p1l = __shfl_up_sync(0xFFFFFFFFu, p1c.y, 1);
        float y0r = __shfl_down_sync(0xFFFFFFFFu, y0c.x, 1);
        float y1r = __shfl_down_sync(0xFFFFFFFFu, y1c.x, 1);
        float p0r = __shfl_down_sync(0xFFFFFFFFu, p0c.x, 1);
        float p1r = __shfl_down_sync(0xFFFFFFFFu, p1c.x, 1);
        if (lload) {           // lane 0, interior: real loads (1-lane wavefront)
            y0l = y0[-1]; y1l = y0[SH - 1];
            p0l = p0[-1]; p1l = p0[SH - 1];
        }
        if (rload) {           // lane 31, interior
            y0r = y0[2]; y1r = y0[SH + 2];
            p0r = p0[2]; p1r = p0[SH + 2];
        }
        if (w0e) { y0l = y0c.x; y1l = y1c.x; p0l = p0c.x; p1l = p1c.x; }
        if (w1e) { y0r = y0c.y; y1r = y1c.y; p0r = p0c.y; p1r = p1c.y; }

        // L1 term
        l1_acc += fabsf(y0c.x - p0c.x) + fabsf(y0c.y - p0c.y)
                + fabsf(y1c.x - p1c.x) + fabsf(y1c.y - p1c.y);

        float tt;
        // D axis (scale^2 = ds2)
        tt = fabsf(y0n.x - y0p.x) - fabsf(p0n.x - p0p.x); gd_acc = fmaf(ds2 * tt, tt, gd_acc);
        tt = fabsf(y0n.y - y0p.y) - fabsf(p0n.y - p0p.y); gd_acc = fmaf(ds2 * tt, tt, gd_acc);
        tt = fabsf(y1n.x - y1p.x) - fabsf(p1n.x - p1p.x); gd_acc = fmaf(ds2 * tt, tt, gd_acc);
        tt = fabsf(y1n.y - y1p.y) - fabsf(p1n.y - p1p.y); gd_acc = fmaf(ds2 * tt, tt, gd_acc);
        // H axis, row h0: grad = s*(row_h1 - row_{h0-1})
        tt = fabsf(y1c.x - yhm.x) - fabsf(p1c.x - phm.x); gd_acc = fmaf(hs0 * tt, tt, gd_acc);
        tt = fabsf(y1c.y - yhm.y) - fabsf(p1c.y - phm.y); gd_acc = fmaf(hs0 * tt, tt, gd_acc);
        // H axis, row h1: grad = s*(row_{h1+1} - row_h0)
        tt = fabsf(yhp.x - y0c.x) - fabsf(php.x - p0c.x); gd_acc = fmaf(hs1 * tt, tt, gd_acc);
        tt = fabsf(yhp.y - y0c.y) - fabsf(php.y - p0c.y); gd_acc = fmaf(hs1 * tt, tt, gd_acc);
        // W axis, row h0
        tt = fabsf(y0c.y - y0l) - fabsf(p0c.y - p0l);     gd_acc = fmaf(wl2 * tt, tt, gd_acc);
        tt = fabsf(y0r - y0c.x) - fabsf(p0r - p0c.x);     gd_acc = fmaf(wr2 * tt, tt, gd_acc);
        // W axis, row h1
        tt = fabsf(y1c.y - y1l) - fabsf(p1c.y - p1l);     gd_acc = fmaf(wl2 * tt, tt, gd_acc);
        tt = fabsf(y1r - y1c.x) - fabsf(p1r - p1c.x);     gd_acc = fmaf(wr2 * tt, tt, gd_acc);

        // Rotate windows, advance
        y0p = y0c; y0c = y0n;
        y1p = y1c; y1c = y1n;
        p0p = p0c; p0c = p0n;
        p1p = p1c; p1c = p1n;
        y0 += SD; p0 += SD;
    }

    // ---- Block reduction ----
    #pragma unroll
    for (int off = 16; off > 0; off >>= 1) {
        l1_acc += __shfl_down_sync(0xFFFFFFFFu, l1_acc, off);
        gd_acc += __shfl_down_sync(0xFFFFFFFFu, gd_acc, off);
    }
    if (lane == 0) { s_a[wid] = l1_acc; s_b[wid] = gd_acc; }
    __syncthreads();

    if (wid == 0) {
        l1_acc = (lane < 8) ? s_a[lane] : 0.0f;
        gd_acc = (lane < 8) ? s_b[lane] : 0.0f;
        #pragma unroll
        for (int off = 4; off > 0; off >>= 1) {
            l1_acc += __shfl_down_sync(0xFFFFFFFFu, l1_acc, off);
            gd_acc += __shfl_down_sync(0xFFFFFFFFu, gd_acc, off);
        }
        if (lane == 0) {
            g_part[blockIdx.x][0] = (double)l1_acc;
            g_part[blockIdx.x][1] = (double)gd_acc;
        }
    }

    // ---- Last-block final reduction ----
    if (threadIdx.x == 0) {
        __threadfence();
        int prev = atomicAdd(&g_count, 1);
        s_last = (prev == NBLK - 1);
    }
    __syncthreads();

    if (s_last) {
        double l1d = 0.0, gdd = 0.0;
        for (int i = threadIdx.x; i < NBLK; i += TPB) {
            l1d += g_part[i][0];
            gdd += g_part[i][1];
        }
        #pragma unroll
        for (int off = 16; off > 0; off >>= 1) {
            l1d += __shfl_down_sync(0xFFFFFFFFu, l1d, off);
            gdd += __shfl_down_sync(0xFFFFFFFFu, gdd, off);
        }
        __shared__ double sh_l1[8];
        __shared__ double sh_gd[8];
        if (lane == 0) { sh_l1[wid] = l1d; sh_gd[wid] = gdd; }
        __syncthreads();
        if (wid == 0) {
            l1d = (lane < 8) ? sh_l1[lane] : 0.0;
            gdd = (lane < 8) ? sh_gd[lane] : 0.0;
            #pragma unroll
            for (int off = 4; off > 0; off >>= 1) {
                l1d += __shfl_down_sync(0xFFFFFFFFu, l1d, off);
                gdd += __shfl_down_sync(0xFFFFFFFFu, gdd, off);
            }
            if (lane == 0) {
                double bce = (double)g_bce / (double)NDSC;
                double l1m = l1d / (double)NTOT;
                double gdm = gdd / (double)NTOT;
                out[0] = (float)(bce + 100.0 * l1m + 100.0 * gdm);
                g_count = 0;   // restore for deterministic graph replay
            }
        }
    }
}

extern "C" void kernel_launch(void* const* d_in, const int* in_sizes, int n_in,
                              void* d_out, int out_size)
{
    const float* dsc_fake = (const float*)d_in[0];
    const float* predicts = (const float*)d_in[1];
    const float* y_data   = (const float*)d_in[2];
    const float* zeros    = (const float*)d_in[3];
    float* out = (float*)d_out;

    vol_kernel<<<NBLK, TPB>>>(predicts, y_data, dsc_fake, zeros, out);
}